// round 10
// baseline (speedup 1.0000x reference)
#include <cuda_runtime.h>
#include <cstdint>

// SimpleGNN: 3x CGConv + mean-pool + linear.
// P[N,512] = H @ B^T (one GEMM/layer, biases folded into dst halves).
// R10: edge-parallel, warp-per-edge, 4 channels/lane with REGISTER-resident
// K=16 weights (64 packed f32x2 regs; no launch_bounds cap -> no spill) and
// red.global.add.v4.f32 scatter (4x fewer atomic lane-ops than scalar RED,
// which R9 showed costs ~490us/layer at 1.29 cyc/lane).

#define NN 50000
#define EE 800000
#define CC 128
#define ZP 512

typedef unsigned long long ull;

__device__ __align__(16) float g_P[(size_t)NN * ZP];   // node projections (+bias on dst halves)
__device__ __align__(16) float g_hA[(size_t)NN * CC];
__device__ __align__(16) float g_hB[(size_t)NN * CC];
__device__ __align__(16) float g_msg[(size_t)NN * CC]; // aggregated messages
__device__ __align__(16) float g_B[ZP * CC];           // packed node-projection weights
__device__ float g_cs[CC];                 // column sums for pooling
__device__ int   g_idx64;                  // 1 if edge_idx is int64, 0 if int32

// ---- f32x2 helpers (sm_100+) ----------------------------------------------
__device__ __forceinline__ ull pack2(float a, float b) {
    ull r; asm("mov.b64 %0, {%1, %2};" : "=l"(r) : "f"(a), "f"(b)); return r;
}
__device__ __forceinline__ void unpack2(ull v, float& a, float& b) {
    asm("mov.b64 {%0, %1}, %2;" : "=f"(a), "=f"(b) : "l"(v));
}
__device__ __forceinline__ ull fma2(ull a, ull b, ull c) {
    ull d; asm("fma.rn.f32x2 %0, %1, %2, %3;" : "=l"(d) : "l"(a), "l"(b), "l"(c));
    return d;
}

// ---------------------------------------------------------------------------
__global__ void detect_k(const long long* __restrict__ e64, int N) {
    if (threadIdx.x == 0 && blockIdx.x == 0) {
        int ok64 = 1;
        for (int i = 0; i < 64; i++) {
            long long v = e64[i];
            if (v < 0 || v >= N) { ok64 = 0; break; }
        }
        g_idx64 = ok64;
    }
}

__device__ __forceinline__ int load_idx(const void* p, long long off) {
    return g_idx64 ? (int)__ldg((const long long*)p + off)
                   : __ldg((const int*)p + off);
}

// ---------------------------------------------------------------------------
// pack the 512x128 node-projection weight matrix:
// rows   0..127 : Wf[:,   0:128] (dst f) | 128..255 : Wf[:,128:256] (src f)
// rows 256..383 : Ws[:,   0:128] (dst s) | 384..511 : Ws[:,128:256] (src s)
__global__ void pack_B(const float* __restrict__ Wf, const float* __restrict__ Ws) {
    int j = blockIdx.x * blockDim.x + threadIdx.x;
    if (j >= ZP * CC) return;
    int row  = j >> 7;
    int k    = j & 127;
    int c    = row & 127;
    int part = row >> 7;
    const float* W = (part < 2) ? Wf : Ws;
    int off = (part & 1) ? 128 : 0;
    g_B[j] = W[c * 272 + off + k];
}

// ---------------------------------------------------------------------------
// P[M,512] = H[M,128] @ g_B^T ; bias folded into dst halves.
__global__ void gemm_k(const float* __restrict__ H,
                       const float* __restrict__ bf,
                       const float* __restrict__ bs, int M) {
    __shared__ float As[32][65];
    __shared__ float Bs[32][65];
    int tid = threadIdx.x;
    int tx = tid & 15, ty = tid >> 4;
    int i0 = blockIdx.x * 64, j0 = blockIdx.y * 64;

    float acc[4][4];
#pragma unroll
    for (int r = 0; r < 4; r++)
#pragma unroll
        for (int p = 0; p < 4; p++) acc[r][p] = 0.f;

    for (int k0 = 0; k0 < 128; k0 += 32) {
#pragma unroll
        for (int rep = 0; rep < 2; rep++) {
            int ii = (tid >> 3) + rep * 32;
            int kk = (tid & 7) << 2;
            int row = i0 + ii;
            float4 va = make_float4(0.f, 0.f, 0.f, 0.f);
            if (row < M) va = *(const float4*)(H + (size_t)row * 128 + k0 + kk);
            As[kk + 0][ii] = va.x; As[kk + 1][ii] = va.y;
            As[kk + 2][ii] = va.z; As[kk + 3][ii] = va.w;
            float4 vb = *(const float4*)(g_B + (size_t)(j0 + ii) * 128 + k0 + kk);
            Bs[kk + 0][ii] = vb.x; Bs[kk + 1][ii] = vb.y;
            Bs[kk + 2][ii] = vb.z; Bs[kk + 3][ii] = vb.w;
        }
        __syncthreads();
#pragma unroll
        for (int kk = 0; kk < 32; kk++) {
            float a[4], b[4];
#pragma unroll
            for (int r = 0; r < 4; r++) a[r] = As[kk][ty * 4 + r];
#pragma unroll
            for (int p = 0; p < 4; p++) b[p] = Bs[kk][tx * 4 + p];
#pragma unroll
            for (int r = 0; r < 4; r++)
#pragma unroll
                for (int p = 0; p < 4; p++) acc[r][p] = fmaf(a[r], b[p], acc[r][p]);
        }
        __syncthreads();
    }

    int col = j0 + tx * 4;
    float4 badd = make_float4(0.f, 0.f, 0.f, 0.f);
    if (col < 128)                badd = *(const float4*)(bf + col);
    else if (col >= 256 && col < 384) badd = *(const float4*)(bs + col - 256);

#pragma unroll
    for (int r = 0; r < 4; r++) {
        int row = i0 + ty * 4 + r;
        if (row < M)
            *(float4*)(g_P + (size_t)row * ZP + col) =
                make_float4(acc[r][0] + badd.x, acc[r][1] + badd.y,
                            acc[r][2] + badd.z, acc[r][3] + badd.w);
    }
}

// ---------------------------------------------------------------------------
__global__ void zero_k(float* __restrict__ p, int n4) {
    float4* q = (float4*)p;
    for (int i = blockIdx.x * blockDim.x + threadIdx.x; i < n4;
         i += gridDim.x * blockDim.x)
        q[i] = make_float4(0.f, 0.f, 0.f, 0.f);
}

__device__ __forceinline__ float sigm(float x) {
    return __fdividef(1.f, 1.f + __expf(-x));
}
__device__ __forceinline__ float sftp(float x) {
    return fmaxf(x, 0.f) + __logf(1.f + __expf(-fabsf(x)));
}

// ---------------------------------------------------------------------------
// Warp-per-edge; lane owns channels 4l..4l+3 (16B-aligned for red.v4).
// Weights: 64 packed f32x2 regs (16 k x 2 channel-pairs x 2 gates), loaded once
// per persistent warp. Per edge: 2 idx + 4 ew LDG + 4 float4 P-gathers,
// 16 packs + 64 FFMA2, 8 MUFU, 1 red.global.add.v4.f32.
__global__ void edge_k(const void* __restrict__ eidx,
                       const float* __restrict__ ew,
                       const float* __restrict__ Wf, const float* __restrict__ Ws,
                       int E) {
    int lane = threadIdx.x & 31;
    int wg   = blockIdx.x * (blockDim.x >> 5) + (threadIdx.x >> 5);
    int nwg  = gridDim.x * (blockDim.x >> 5);
    int c0   = lane * 4;

    // register-resident weights: [k][channel-pair] for each gate
    ull wfA[16], wfB[16], wsA[16], wsB[16];
#pragma unroll
    for (int k = 0; k < 16; k++) {
        wfA[k] = pack2(__ldg(Wf + (size_t)(c0 + 0) * 272 + 256 + k),
                       __ldg(Wf + (size_t)(c0 + 1) * 272 + 256 + k));
        wfB[k] = pack2(__ldg(Wf + (size_t)(c0 + 2) * 272 + 256 + k),
                       __ldg(Wf + (size_t)(c0 + 3) * 272 + 256 + k));
        wsA[k] = pack2(__ldg(Ws + (size_t)(c0 + 0) * 272 + 256 + k),
                       __ldg(Ws + (size_t)(c0 + 1) * 272 + 256 + k));
        wsB[k] = pack2(__ldg(Ws + (size_t)(c0 + 2) * 272 + 256 + k),
                       __ldg(Ws + (size_t)(c0 + 3) * 272 + 256 + k));
    }

#pragma unroll 2
    for (int e = wg; e < E; e += nwg) {
        int s = load_idx(eidx, e);
        int d = load_idx(eidx, (long long)E + e);

        const float4* ewp = (const float4*)(ew + (size_t)e * 16);
        float4 w0 = __ldg(ewp + 0), w1 = __ldg(ewp + 1);
        float4 w2 = __ldg(ewp + 2), w3 = __ldg(ewp + 3);
        float ev[16] = {w0.x, w0.y, w0.z, w0.w, w1.x, w1.y, w1.z, w1.w,
                        w2.x, w2.y, w2.z, w2.w, w3.x, w3.y, w3.z, w3.w};

        const float* Pd = g_P + (size_t)d * ZP;
        const float* Ps = g_P + (size_t)s * ZP;
        float4 fd = *(const float4*)(Pd + c0);          // dst f (+bias)
        float4 fs = *(const float4*)(Ps + 128 + c0);    // src f
        float4 sd = *(const float4*)(Pd + 256 + c0);    // dst s (+bias)
        float4 ss = *(const float4*)(Ps + 384 + c0);    // src s

        ull FA = pack2(fd.x + fs.x, fd.y + fs.y);
        ull FB = pack2(fd.z + fs.z, fd.w + fs.w);
        ull SA = pack2(sd.x + ss.x, sd.y + ss.y);
        ull SB = pack2(sd.z + ss.z, sd.w + ss.w);

#pragma unroll
        for (int k = 0; k < 16; k++) {
            ull wv = pack2(ev[k], ev[k]);
            FA = fma2(wv, wfA[k], FA);
            FB = fma2(wv, wfB[k], FB);
            SA = fma2(wv, wsA[k], SA);
            SB = fma2(wv, wsB[k], SB);
        }

        float f0, f1, f2, f3, s0, s1, s2, s3;
        unpack2(FA, f0, f1); unpack2(FB, f2, f3);
        unpack2(SA, s0, s1); unpack2(SB, s2, s3);

        float m0 = sigm(f0) * sftp(s0);
        float m1 = sigm(f1) * sftp(s1);
        float m2 = sigm(f2) * sftp(s2);
        float m3 = sigm(f3) * sftp(s3);

        float* outp = g_msg + (size_t)d * CC + c0;
        asm volatile("red.global.add.v4.f32 [%0], {%1,%2,%3,%4};"
                     :: "l"(outp), "f"(m0), "f"(m1), "f"(m2), "f"(m3)
                     : "memory");
    }
}

// ---------------------------------------------------------------------------
__global__ void combine_k(const float* __restrict__ h, float* __restrict__ o,
                          int n4, int relu) {
    const float4* h4 = (const float4*)h;
    const float4* m4 = (const float4*)g_msg;
    float4* o4 = (float4*)o;
    for (int i = blockIdx.x * blockDim.x + threadIdx.x; i < n4;
         i += gridDim.x * blockDim.x) {
        float4 a = h4[i], b = m4[i];
        a.x += b.x; a.y += b.y; a.z += b.z; a.w += b.w;
        if (relu) {
            a.x = fmaxf(a.x, 0.f); a.y = fmaxf(a.y, 0.f);
            a.z = fmaxf(a.z, 0.f); a.w = fmaxf(a.w, 0.f);
        }
        o4[i] = a;
    }
}

// ---------------------------------------------------------------------------
__global__ void colsum_k(const float* __restrict__ h, int M) {
    int c = threadIdx.x;   // 128 threads
    float loc = 0.f;
    for (int i = blockIdx.x; i < M; i += gridDim.x)
        loc += h[(size_t)i * CC + c];
    atomicAdd(&g_cs[c], loc);
}

__global__ void final_k(const float* __restrict__ Wlin,
                        const float* __restrict__ blin,
                        float* __restrict__ out, float invM) {
    int o = threadIdx.x;
    if (o < 64) {
        float a = 0.f;
#pragma unroll 4
        for (int c = 0; c < 128; c++) a += g_cs[c] * Wlin[o * 128 + c];
        out[o] = blin[o] + a * invM;
    }
}

// ---------------------------------------------------------------------------
extern "C" void kernel_launch(void* const* d_in, const int* in_sizes, int n_in,
                              void* d_out, int out_size) {
    const float* x    = (const float*)d_in[0];
    const void*  eidx = d_in[1];
    const float* ew   = (const float*)d_in[2];
    const float* Wf[3] = {(const float*)d_in[3], (const float*)d_in[7],  (const float*)d_in[11]};
    const float* bf[3] = {(const float*)d_in[4], (const float*)d_in[8],  (const float*)d_in[12]};
    const float* Ws[3] = {(const float*)d_in[5], (const float*)d_in[9],  (const float*)d_in[13]};
    const float* bs[3] = {(const float*)d_in[6], (const float*)d_in[10], (const float*)d_in[14]};
    const float* Wlin = (const float*)d_in[15];
    const float* blin = (const float*)d_in[16];
    float* out = (float*)d_out;

    int M = in_sizes[0] / 128;   // 50000
    int E = in_sizes[2] / 16;    // 800000

    float *hA, *hB, *msg, *cs;
    cudaGetSymbolAddress((void**)&hA,  g_hA);
    cudaGetSymbolAddress((void**)&hB,  g_hB);
    cudaGetSymbolAddress((void**)&msg, g_msg);
    cudaGetSymbolAddress((void**)&cs,  g_cs);

    const float* hin[3]  = {x, hA, hB};
    float*       hout[3] = {hA, hB, hA};

    dim3 ggrid((M + 63) / 64, 8);
    int n4 = M * CC / 4;

    detect_k<<<1, 32>>>((const long long*)eidx, M);

    for (int l = 0; l < 3; l++) {
        pack_B<<<(ZP * CC + 255) / 256, 256>>>(Wf[l], Ws[l]);
        gemm_k<<<ggrid, 256>>>(hin[l], bf[l], bs[l], M);
        zero_k<<<1024, 256>>>(msg, n4);
        // 128-thread blocks (4 warps): higher blocks/SM residency under
        // ~170-200 regs/thread than 256-thread blocks.
        edge_k<<<2368, 128>>>(eidx, ew, Wf[l], Ws[l], E);
        combine_k<<<1024, 256>>>(hin[l], hout[l], n4, (l < 2) ? 1 : 0);
    }

    zero_k<<<1, 32>>>(cs, CC / 4);
    colsum_k<<<512, 128>>>(hA, M);
    final_k<<<1, 64>>>(Wlin, blin, out, 1.0f / (float)M);
}

// round 11
// speedup vs baseline: 1.1151x; 1.1151x over previous
#include <cuda_runtime.h>
#include <cstdint>

// SimpleGNN: 3x CGConv + mean-pool + linear.
// P[N,512] = H @ B^T (one GEMM/layer, biases folded into dst halves).
// R11: NO ATOMICS. Edge kernel (R9 structure: warp-task=(edge,quarter),
// 1 ch/lane, 16-ull register weights, f32x2 FMA) writes each message to its
// CSR slot with a plain coalesced STG. A separate agg kernel (warp-per-node)
// reads the contiguous, address-linear message rows and fuses residual+ReLU.

#define NN 50000
#define EE 800000
#define CC 128
#define ZP 512

typedef unsigned long long ull;

__device__ __align__(16) float g_P[(size_t)NN * ZP];    // node projections (+bias dst halves)
__device__ __align__(16) float g_hA[(size_t)NN * CC];
__device__ __align__(16) float g_hB[(size_t)NN * CC];
__device__ __align__(16) float g_mb[(size_t)EE * CC];   // per-edge messages, CSR slots (409.6MB)
__device__ __align__(16) float g_B[ZP * CC];            // packed node-projection weights
__device__ float g_cs[CC];                 // column sums for pooling
__device__ int   g_idx64;                  // 1 if edge_idx is int64, 0 if int32
__device__ int   g_start[NN + 1];          // CSR row offsets (by dst)
__device__ int   g_cur[NN];                // histogram / scatter cursor
__device__ int   g_pose[EE];               // CSR slot of each edge (natural order)
__device__ int   g_bsum[256];              // scan block sums
__device__ int   g_boff[256];              // scan block offsets

// ---- f32x2 helpers (sm_100+) ----------------------------------------------
__device__ __forceinline__ void unpack2(ull v, float& a, float& b) {
    asm("mov.b64 {%0, %1}, %2;" : "=f"(a), "=f"(b) : "l"(v));
}
__device__ __forceinline__ ull fma2(ull a, ull b, ull c) {
    ull d; asm("fma.rn.f32x2 %0, %1, %2, %3;" : "=l"(d) : "l"(a), "l"(b), "l"(c));
    return d;
}

// ---------------------------------------------------------------------------
__global__ void detect_k(const long long* __restrict__ e64, int N) {
    if (threadIdx.x == 0 && blockIdx.x == 0) {
        int ok64 = 1;
        for (int i = 0; i < 64; i++) {
            long long v = e64[i];
            if (v < 0 || v >= N) { ok64 = 0; break; }
        }
        g_idx64 = ok64;
    }
}

__device__ __forceinline__ int load_idx(const void* p, long long off) {
    return g_idx64 ? (int)__ldg((const long long*)p + off)
                   : __ldg((const int*)p + off);
}

// ---------------------------------------------------------------------------
__global__ void zero_int_k(int* __restrict__ p, int n) {
    for (int i = blockIdx.x * blockDim.x + threadIdx.x; i < n;
         i += gridDim.x * blockDim.x) p[i] = 0;
}

__global__ void count_k(const void* __restrict__ eidx, int E) {
    for (int e = blockIdx.x * blockDim.x + threadIdx.x; e < E;
         e += gridDim.x * blockDim.x) {
        int d = load_idx(eidx, (long long)E + e);
        atomicAdd(&g_cur[d], 1);
    }
}

// hierarchical scan (3 kernels, ~15us total)
__global__ void scan1_k(int N) {
    __shared__ int sh[256];
    int t = threadIdx.x;
    int i = blockIdx.x * 256 + t;
    int v = (i < N) ? g_cur[i] : 0;
    sh[t] = v;
    __syncthreads();
#pragma unroll
    for (int off = 1; off < 256; off <<= 1) {
        int u = (t >= off) ? sh[t - off] : 0;
        __syncthreads();
        sh[t] += u;
        __syncthreads();
    }
    if (i < N) g_start[i] = sh[t] - v;
    if (t == 255) g_bsum[blockIdx.x] = sh[255];
}

__global__ void scan2_k(int nblk) {
    __shared__ int sh[256];
    int t = threadIdx.x;
    int v = (t < nblk) ? g_bsum[t] : 0;
    sh[t] = v;
    __syncthreads();
#pragma unroll
    for (int off = 1; off < 256; off <<= 1) {
        int u = (t >= off) ? sh[t - off] : 0;
        __syncthreads();
        sh[t] += u;
        __syncthreads();
    }
    g_boff[t] = sh[t] - v;
}

__global__ void scan3_k(int N, int E) {
    int i = blockIdx.x * blockDim.x + threadIdx.x;
    if (i < N) {
        g_start[i] += g_boff[i >> 8];
        g_cur[i] = 0;
    }
    if (i == 0) g_start[N] = E;
}

// assign each edge its CSR slot
__global__ void scatter_k(const void* __restrict__ eidx, int E) {
    for (int e = blockIdx.x * blockDim.x + threadIdx.x; e < E;
         e += gridDim.x * blockDim.x) {
        int d = load_idx(eidx, (long long)E + e);
        g_pose[e] = g_start[d] + atomicAdd(&g_cur[d], 1);
    }
}

// ---------------------------------------------------------------------------
// pack the 512x128 node-projection weight matrix:
// rows   0..127 : Wf[:,   0:128] (dst f) | 128..255 : Wf[:,128:256] (src f)
// rows 256..383 : Ws[:,   0:128] (dst s) | 384..511 : Ws[:,128:256] (src s)
__global__ void pack_B(const float* __restrict__ Wf, const float* __restrict__ Ws) {
    int j = blockIdx.x * blockDim.x + threadIdx.x;
    if (j >= ZP * CC) return;
    int row  = j >> 7;
    int k    = j & 127;
    int c    = row & 127;
    int part = row >> 7;
    const float* W = (part < 2) ? Wf : Ws;
    int off = (part & 1) ? 128 : 0;
    g_B[j] = W[c * 272 + off + k];
}

// ---------------------------------------------------------------------------
// P[M,512] = H[M,128] @ g_B^T ; bias folded into dst halves.
__global__ void gemm_k(const float* __restrict__ H,
                       const float* __restrict__ bf,
                       const float* __restrict__ bs, int M) {
    __shared__ float As[32][65];
    __shared__ float Bs[32][65];
    int tid = threadIdx.x;
    int tx = tid & 15, ty = tid >> 4;
    int i0 = blockIdx.x * 64, j0 = blockIdx.y * 64;

    float acc[4][4];
#pragma unroll
    for (int r = 0; r < 4; r++)
#pragma unroll
        for (int p = 0; p < 4; p++) acc[r][p] = 0.f;

    for (int k0 = 0; k0 < 128; k0 += 32) {
#pragma unroll
        for (int rep = 0; rep < 2; rep++) {
            int ii = (tid >> 3) + rep * 32;
            int kk = (tid & 7) << 2;
            int row = i0 + ii;
            float4 va = make_float4(0.f, 0.f, 0.f, 0.f);
            if (row < M) va = *(const float4*)(H + (size_t)row * 128 + k0 + kk);
            As[kk + 0][ii] = va.x; As[kk + 1][ii] = va.y;
            As[kk + 2][ii] = va.z; As[kk + 3][ii] = va.w;
            float4 vb = *(const float4*)(g_B + (size_t)(j0 + ii) * 128 + k0 + kk);
            Bs[kk + 0][ii] = vb.x; Bs[kk + 1][ii] = vb.y;
            Bs[kk + 2][ii] = vb.z; Bs[kk + 3][ii] = vb.w;
        }
        __syncthreads();
#pragma unroll
        for (int kk = 0; kk < 32; kk++) {
            float a[4], b[4];
#pragma unroll
            for (int r = 0; r < 4; r++) a[r] = As[kk][ty * 4 + r];
#pragma unroll
            for (int p = 0; p < 4; p++) b[p] = Bs[kk][tx * 4 + p];
#pragma unroll
            for (int r = 0; r < 4; r++)
#pragma unroll
                for (int p = 0; p < 4; p++) acc[r][p] = fmaf(a[r], b[p], acc[r][p]);
        }
        __syncthreads();
    }

    int col = j0 + tx * 4;
    float4 badd = make_float4(0.f, 0.f, 0.f, 0.f);
    if (col < 128)                badd = *(const float4*)(bf + col);
    else if (col >= 256 && col < 384) badd = *(const float4*)(bs + col - 256);

#pragma unroll
    for (int r = 0; r < 4; r++) {
        int row = i0 + ty * 4 + r;
        if (row < M)
            *(float4*)(g_P + (size_t)row * ZP + col) =
                make_float4(acc[r][0] + badd.x, acc[r][1] + badd.y,
                            acc[r][2] + badd.z, acc[r][3] + badd.w);
    }
}

// ---------------------------------------------------------------------------
__global__ void zero_k(float* __restrict__ p, int n4) {
    float4* q = (float4*)p;
    for (int i = blockIdx.x * blockDim.x + threadIdx.x; i < n4;
         i += gridDim.x * blockDim.x)
        q[i] = make_float4(0.f, 0.f, 0.f, 0.f);
}

__device__ __forceinline__ float sigm(float x) {
    return __fdividef(1.f, 1.f + __expf(-x));
}
__device__ __forceinline__ float sftp(float x) {
    return fmaxf(x, 0.f) + __logf(1.f + __expf(-fabsf(x)));
}

// ---------------------------------------------------------------------------
// Warp task = (edge, quarter). Lane owns channel c = 32*q + lane.
// 16-ull register weights (k-paired, matches packed ew pairs -> zero pack MOVs).
// Message written with a plain coalesced STG.32 to the edge's CSR slot.
__global__ void edge_k(const void* __restrict__ eidx,
                       const float* __restrict__ ew,
                       const float* __restrict__ Wf, const float* __restrict__ Ws,
                       int E) {
    int lane = threadIdx.x & 31;
    int wg   = blockIdx.x * (blockDim.x >> 5) + (threadIdx.x >> 5);
    int nwg  = gridDim.x * (blockDim.x >> 5);   // multiple of 4 by construction
    int q    = wg & 3;
    int c    = q * 32 + lane;                   // this lane's channel

    // register-resident K-weights: 8 f32x2 per gate (pairs along k)
    ull wf2[8], ws2[8];
    {
        const ulonglong2* wfp = (const ulonglong2*)(Wf + (size_t)c * 272 + 256);
        const ulonglong2* wsp = (const ulonglong2*)(Ws + (size_t)c * 272 + 256);
#pragma unroll
        for (int i = 0; i < 4; i++) {
            ulonglong2 a = __ldg(wfp + i);
            wf2[2 * i] = a.x; wf2[2 * i + 1] = a.y;
            ulonglong2 b = __ldg(wsp + i);
            ws2[2 * i] = b.x; ws2[2 * i + 1] = b.y;
        }
    }

    for (int e = wg >> 2; e < E; e += nwg >> 2) {
        int s   = load_idx(eidx, e);
        int d   = load_idx(eidx, (long long)E + e);
        int pos = __ldg(g_pose + e);

        const ulonglong2* ewp = (const ulonglong2*)(ew + (size_t)e * 16);
        ulonglong2 e0 = __ldg(ewp + 0), e1 = __ldg(ewp + 1);
        ulonglong2 e2 = __ldg(ewp + 2), e3 = __ldg(ewp + 3);

        const float* Pd = g_P + (size_t)d * ZP;
        const float* Ps = g_P + (size_t)s * ZP;
        float fd = __ldg(Pd + c);          // dst f (bias folded)
        float sd = __ldg(Pd + 256 + c);    // dst s (bias folded)
        float fs = __ldg(Ps + 128 + c);    // src f
        float ss = __ldg(Ps + 384 + c);    // src s

        ull FF = 0, SS = 0;   // (0.f, 0.f) packed
        FF = fma2(e0.x, wf2[0], FF);  SS = fma2(e0.x, ws2[0], SS);
        FF = fma2(e0.y, wf2[1], FF);  SS = fma2(e0.y, ws2[1], SS);
        FF = fma2(e1.x, wf2[2], FF);  SS = fma2(e1.x, ws2[2], SS);
        FF = fma2(e1.y, wf2[3], FF);  SS = fma2(e1.y, ws2[3], SS);
        FF = fma2(e2.x, wf2[4], FF);  SS = fma2(e2.x, ws2[4], SS);
        FF = fma2(e2.y, wf2[5], FF);  SS = fma2(e2.y, ws2[5], SS);
        FF = fma2(e3.x, wf2[6], FF);  SS = fma2(e3.x, ws2[6], SS);
        FF = fma2(e3.y, wf2[7], FF);  SS = fma2(e3.y, ws2[7], SS);

        float flo, fhi, slo, shi;
        unpack2(FF, flo, fhi);
        unpack2(SS, slo, shi);
        float F = fd + fs + flo + fhi;
        float S = sd + ss + slo + shi;
        float m = sigm(F) * sftp(S);

        g_mb[(size_t)pos * CC + c] = m;    // plain coalesced store, no atomic
    }
}

// ---------------------------------------------------------------------------
// Warp per node; lane owns channels 4l..4l+3. Message rows for node n live at
// contiguous CSR slots [start[n], start[n+1]) -> address-linear float4 reads,
// fully pipelinable (no dependent gathers). Fuses residual + ReLU.
__global__ void agg_k(const float* __restrict__ hin, float* __restrict__ hout,
                      int M, int relu) {
    int lane = threadIdx.x & 31;
    int wg   = blockIdx.x * (blockDim.x >> 5) + (threadIdx.x >> 5);
    int nwg  = gridDim.x * (blockDim.x >> 5);

    for (int n = wg; n < M; n += nwg) {
        int j0 = __ldg(g_start + n), j1 = __ldg(g_start + n + 1);
        float4 acc = make_float4(0.f, 0.f, 0.f, 0.f);
        for (int j = j0; j < j1; j++) {
            float4 v = *(const float4*)(g_mb + (size_t)j * CC + lane * 4);
            acc.x += v.x; acc.y += v.y; acc.z += v.z; acc.w += v.w;
        }
        float4 h = *(const float4*)(hin + (size_t)n * CC + lane * 4);
        h.x += acc.x; h.y += acc.y; h.z += acc.z; h.w += acc.w;
        if (relu) {
            h.x = fmaxf(h.x, 0.f); h.y = fmaxf(h.y, 0.f);
            h.z = fmaxf(h.z, 0.f); h.w = fmaxf(h.w, 0.f);
        }
        *(float4*)(hout + (size_t)n * CC + lane * 4) = h;
    }
}

// ---------------------------------------------------------------------------
__global__ void colsum_k(const float* __restrict__ h, int M) {
    int c = threadIdx.x;   // 128 threads
    float loc = 0.f;
    for (int i = blockIdx.x; i < M; i += gridDim.x)
        loc += h[(size_t)i * CC + c];
    atomicAdd(&g_cs[c], loc);
}

__global__ void final_k(const float* __restrict__ Wlin,
                        const float* __restrict__ blin,
                        float* __restrict__ out, float invM) {
    int o = threadIdx.x;
    if (o < 64) {
        float a = 0.f;
#pragma unroll 4
        for (int c = 0; c < 128; c++) a += g_cs[c] * Wlin[o * 128 + c];
        out[o] = blin[o] + a * invM;
    }
}

// ---------------------------------------------------------------------------
extern "C" void kernel_launch(void* const* d_in, const int* in_sizes, int n_in,
                              void* d_out, int out_size) {
    const float* x    = (const float*)d_in[0];
    const void*  eidx = d_in[1];
    const float* ew   = (const float*)d_in[2];
    const float* Wf[3] = {(const float*)d_in[3], (const float*)d_in[7],  (const float*)d_in[11]};
    const float* bf[3] = {(const float*)d_in[4], (const float*)d_in[8],  (const float*)d_in[12]};
    const float* Ws[3] = {(const float*)d_in[5], (const float*)d_in[9],  (const float*)d_in[13]};
    const float* bs[3] = {(const float*)d_in[6], (const float*)d_in[10], (const float*)d_in[14]};
    const float* Wlin = (const float*)d_in[15];
    const float* blin = (const float*)d_in[16];
    float* out = (float*)d_out;

    int M = in_sizes[0] / 128;   // 50000
    int E = in_sizes[2] / 16;    // 800000

    float *hA, *hB, *cs;
    int *cur;
    cudaGetSymbolAddress((void**)&hA,  g_hA);
    cudaGetSymbolAddress((void**)&hB,  g_hB);
    cudaGetSymbolAddress((void**)&cs,  g_cs);
    cudaGetSymbolAddress((void**)&cur, g_cur);

    const float* hin[3]  = {x, hA, hB};
    float*       hout[3] = {hA, hB, hA};

    dim3 ggrid((M + 63) / 64, 8);
    int nblk = (M + 255) / 256;

    // ---- CSR slot assignment (once per launch) ----
    detect_k<<<1, 32>>>((const long long*)eidx, M);
    zero_int_k<<<256, 256>>>(cur, M);
    count_k<<<1024, 256>>>(eidx, E);
    scan1_k<<<nblk, 256>>>(M);
    scan2_k<<<1, 256>>>(nblk);
    scan3_k<<<nblk, 256>>>(M, E);
    scatter_k<<<1024, 256>>>(eidx, E);

    // ---- 3 CGConv layers ----
    for (int l = 0; l < 3; l++) {
        pack_B<<<(ZP * CC + 255) / 256, 256>>>(Wf[l], Ws[l]);
        gemm_k<<<ggrid, 256>>>(hin[l], bf[l], bs[l], M);
        edge_k<<<2368, 256>>>(eidx, ew, Wf[l], Ws[l], E);
        agg_k<<<(M + 7) / 8, 256>>>(hin[l], hout[l], M, (l < 2) ? 1 : 0);
    }

    // ---- mean pool + linear ----
    zero_k<<<1, 32>>>(cs, CC / 4);
    colsum_k<<<512, 128>>>(hA, M);
    final_k<<<1, 64>>>(Wlin, blin, out, 1.0f / (float)M);
}

// round 12
// speedup vs baseline: 1.2913x; 1.1581x over previous
#include <cuda_runtime.h>
#include <cstdint>

// SimpleGNN: 3x CGConv + mean-pool + linear.
// P[N,512] = H @ B^T (one GEMM/layer, biases folded into dst halves).
// R12: CSR-ordered edge processing with RUN-ACCUMULATED scatter. Warp task =
// (chunk of 8 CSR slots, quarter); 1 ch/lane with 16-ull register weights
// (R9's proven no-spill compute); messages for the same dst accumulate in a
// register; scalar red.global.add.f32 fires only at dst-run boundaries
// (~0.19 RED/edge vs R9's 1/edge which cost ~490us/layer).

#define NN 50000
#define EE 800000
#define CC 128
#define ZP 512

typedef unsigned long long ull;

__device__ __align__(16) float g_P[(size_t)NN * ZP];    // node projections (+bias dst halves)
__device__ __align__(16) float g_hA[(size_t)NN * CC];
__device__ __align__(16) float g_hB[(size_t)NN * CC];
__device__ __align__(16) float g_msg[(size_t)NN * CC];  // aggregated messages
__device__ __align__(16) float g_B[ZP * CC];            // packed node-projection weights
__device__ __align__(16) float g_ewc[(size_t)EE * 16];  // ew permuted into CSR order
__device__ float g_cs[CC];                 // column sums for pooling
__device__ int   g_idx64;                  // 1 if edge_idx is int64, 0 if int32
__device__ int   g_start[NN + 1];          // CSR row offsets (by dst)
__device__ int   g_cur[NN];                // histogram / scatter cursor
__device__ int   g_srcp[EE];               // CSR: src node per slot
__device__ int   g_dstp[EE];               // CSR: dst node per slot
__device__ int   g_bsum[256];              // scan block sums
__device__ int   g_boff[256];              // scan block offsets

// ---- f32x2 helpers (sm_100+) ----------------------------------------------
__device__ __forceinline__ void unpack2(ull v, float& a, float& b) {
    asm("mov.b64 {%0, %1}, %2;" : "=f"(a), "=f"(b) : "l"(v));
}
__device__ __forceinline__ ull fma2(ull a, ull b, ull c) {
    ull d; asm("fma.rn.f32x2 %0, %1, %2, %3;" : "=l"(d) : "l"(a), "l"(b), "l"(c));
    return d;
}

// ---------------------------------------------------------------------------
__global__ void detect_k(const long long* __restrict__ e64, int N) {
    if (threadIdx.x == 0 && blockIdx.x == 0) {
        int ok64 = 1;
        for (int i = 0; i < 64; i++) {
            long long v = e64[i];
            if (v < 0 || v >= N) { ok64 = 0; break; }
        }
        g_idx64 = ok64;
    }
}

__device__ __forceinline__ int load_idx(const void* p, long long off) {
    return g_idx64 ? (int)__ldg((const long long*)p + off)
                   : __ldg((const int*)p + off);
}

// ---------------------------------------------------------------------------
__global__ void zero_int_k(int* __restrict__ p, int n) {
    for (int i = blockIdx.x * blockDim.x + threadIdx.x; i < n;
         i += gridDim.x * blockDim.x) p[i] = 0;
}

__global__ void count_k(const void* __restrict__ eidx, int E) {
    for (int e = blockIdx.x * blockDim.x + threadIdx.x; e < E;
         e += gridDim.x * blockDim.x) {
        int d = load_idx(eidx, (long long)E + e);
        atomicAdd(&g_cur[d], 1);
    }
}

// hierarchical scan (3 kernels, ~15us total)
__global__ void scan1_k(int N) {
    __shared__ int sh[256];
    int t = threadIdx.x;
    int i = blockIdx.x * 256 + t;
    int v = (i < N) ? g_cur[i] : 0;
    sh[t] = v;
    __syncthreads();
#pragma unroll
    for (int off = 1; off < 256; off <<= 1) {
        int u = (t >= off) ? sh[t - off] : 0;
        __syncthreads();
        sh[t] += u;
        __syncthreads();
    }
    if (i < N) g_start[i] = sh[t] - v;
    if (t == 255) g_bsum[blockIdx.x] = sh[255];
}

__global__ void scan2_k(int nblk) {
    __shared__ int sh[256];
    int t = threadIdx.x;
    int v = (t < nblk) ? g_bsum[t] : 0;
    sh[t] = v;
    __syncthreads();
#pragma unroll
    for (int off = 1; off < 256; off <<= 1) {
        int u = (t >= off) ? sh[t - off] : 0;
        __syncthreads();
        sh[t] += u;
        __syncthreads();
    }
    g_boff[t] = sh[t] - v;
}

__global__ void scan3_k(int N, int E) {
    int i = blockIdx.x * blockDim.x + threadIdx.x;
    if (i < N) {
        g_start[i] += g_boff[i >> 8];
        g_cur[i] = 0;
    }
    if (i == 0) g_start[N] = E;
}

// scatter: CSR src/dst lists + ew permuted into CSR order
__global__ void scatter_k(const void* __restrict__ eidx,
                          const float* __restrict__ ew, int E) {
    for (int e = blockIdx.x * blockDim.x + threadIdx.x; e < E;
         e += gridDim.x * blockDim.x) {
        int s = load_idx(eidx, e);
        int d = load_idx(eidx, (long long)E + e);
        int pos = g_start[d] + atomicAdd(&g_cur[d], 1);
        g_srcp[pos] = s;
        g_dstp[pos] = d;
        const float4* src4 = (const float4*)(ew + (size_t)e * 16);
        float4* dst4 = (float4*)(g_ewc + (size_t)pos * 16);
        dst4[0] = src4[0]; dst4[1] = src4[1];
        dst4[2] = src4[2]; dst4[3] = src4[3];
    }
}

// ---------------------------------------------------------------------------
// pack the 512x128 node-projection weight matrix:
// rows   0..127 : Wf[:,   0:128] (dst f) | 128..255 : Wf[:,128:256] (src f)
// rows 256..383 : Ws[:,   0:128] (dst s) | 384..511 : Ws[:,128:256] (src s)
__global__ void pack_B(const float* __restrict__ Wf, const float* __restrict__ Ws) {
    int j = blockIdx.x * blockDim.x + threadIdx.x;
    if (j >= ZP * CC) return;
    int row  = j >> 7;
    int k    = j & 127;
    int c    = row & 127;
    int part = row >> 7;
    const float* W = (part < 2) ? Wf : Ws;
    int off = (part & 1) ? 128 : 0;
    g_B[j] = W[c * 272 + off + k];
}

// ---------------------------------------------------------------------------
// P[M,512] = H[M,128] @ g_B^T ; bias folded into dst halves.
__global__ void gemm_k(const float* __restrict__ H,
                       const float* __restrict__ bf,
                       const float* __restrict__ bs, int M) {
    __shared__ float As[32][65];
    __shared__ float Bs[32][65];
    int tid = threadIdx.x;
    int tx = tid & 15, ty = tid >> 4;
    int i0 = blockIdx.x * 64, j0 = blockIdx.y * 64;

    float acc[4][4];
#pragma unroll
    for (int r = 0; r < 4; r++)
#pragma unroll
        for (int p = 0; p < 4; p++) acc[r][p] = 0.f;

    for (int k0 = 0; k0 < 128; k0 += 32) {
#pragma unroll
        for (int rep = 0; rep < 2; rep++) {
            int ii = (tid >> 3) + rep * 32;
            int kk = (tid & 7) << 2;
            int row = i0 + ii;
            float4 va = make_float4(0.f, 0.f, 0.f, 0.f);
            if (row < M) va = *(const float4*)(H + (size_t)row * 128 + k0 + kk);
            As[kk + 0][ii] = va.x; As[kk + 1][ii] = va.y;
            As[kk + 2][ii] = va.z; As[kk + 3][ii] = va.w;
            float4 vb = *(const float4*)(g_B + (size_t)(j0 + ii) * 128 + k0 + kk);
            Bs[kk + 0][ii] = vb.x; Bs[kk + 1][ii] = vb.y;
            Bs[kk + 2][ii] = vb.z; Bs[kk + 3][ii] = vb.w;
        }
        __syncthreads();
#pragma unroll
        for (int kk = 0; kk < 32; kk++) {
            float a[4], b[4];
#pragma unroll
            for (int r = 0; r < 4; r++) a[r] = As[kk][ty * 4 + r];
#pragma unroll
            for (int p = 0; p < 4; p++) b[p] = Bs[kk][tx * 4 + p];
#pragma unroll
            for (int r = 0; r < 4; r++)
#pragma unroll
                for (int p = 0; p < 4; p++) acc[r][p] = fmaf(a[r], b[p], acc[r][p]);
        }
        __syncthreads();
    }

    int col = j0 + tx * 4;
    float4 badd = make_float4(0.f, 0.f, 0.f, 0.f);
    if (col < 128)                badd = *(const float4*)(bf + col);
    else if (col >= 256 && col < 384) badd = *(const float4*)(bs + col - 256);

#pragma unroll
    for (int r = 0; r < 4; r++) {
        int row = i0 + ty * 4 + r;
        if (row < M)
            *(float4*)(g_P + (size_t)row * ZP + col) =
                make_float4(acc[r][0] + badd.x, acc[r][1] + badd.y,
                            acc[r][2] + badd.z, acc[r][3] + badd.w);
    }
}

// ---------------------------------------------------------------------------
__global__ void zero_k(float* __restrict__ p, int n4) {
    float4* q = (float4*)p;
    for (int i = blockIdx.x * blockDim.x + threadIdx.x; i < n4;
         i += gridDim.x * blockDim.x)
        q[i] = make_float4(0.f, 0.f, 0.f, 0.f);
}

__device__ __forceinline__ float sigm(float x) {
    return __fdividef(1.f, 1.f + __expf(-x));
}
__device__ __forceinline__ float sftp(float x) {
    return fmaxf(x, 0.f) + __logf(1.f + __expf(-fabsf(x)));
}

// ---------------------------------------------------------------------------
// Warp task = (chunk of 8 CSR slots, quarter). Lane owns channel c = 32q+lane.
// 16-ull register weights (k-paired to match packed ew pairs). Messages for a
// dst-run accumulate in a register; one scalar RED per run boundary (uniform
// branch). srcp/dstp/ewc reads are sequential; per-chunk gathers independent.
__global__ void edge_k(const float* __restrict__ Wf, const float* __restrict__ Ws,
                       int E) {
    int lane = threadIdx.x & 31;
    int wg   = blockIdx.x * (blockDim.x >> 5) + (threadIdx.x >> 5);
    int nwg  = gridDim.x * (blockDim.x >> 5);   // multiple of 4 by construction
    int q    = wg & 3;
    int c    = q * 32 + lane;                   // this lane's channel

    // register-resident K-weights: 8 f32x2 per gate (pairs along k)
    ull wf2[8], ws2[8];
    {
        const ulonglong2* wfp = (const ulonglong2*)(Wf + (size_t)c * 272 + 256);
        const ulonglong2* wsp = (const ulonglong2*)(Ws + (size_t)c * 272 + 256);
#pragma unroll
        for (int i = 0; i < 4; i++) {
            ulonglong2 a = __ldg(wfp + i);
            wf2[2 * i] = a.x; wf2[2 * i + 1] = a.y;
            ulonglong2 b = __ldg(wsp + i);
            ws2[2 * i] = b.x; ws2[2 * i + 1] = b.y;
        }
    }

    int nchunk = (E + 7) >> 3;
    for (int ch = wg >> 2; ch < nchunk; ch += nwg >> 2) {
        int base = ch << 3;
        int cnt  = E - base; if (cnt > 8) cnt = 8;

        int   curd = __ldg(g_dstp + base);
        float fd = __ldg(g_P + (size_t)curd * ZP + c);
        float sd = __ldg(g_P + (size_t)curd * ZP + 256 + c);
        float acc = 0.f;

#pragma unroll
        for (int jj = 0; jj < 8; jj++) {
            if (jj >= cnt) break;            // uniform across warp
            int j = base + jj;
            int dd = __ldg(g_dstp + j);      // uniform
            if (dd != curd) {                // uniform branch
                asm volatile("red.global.add.f32 [%0], %1;"
                             :: "l"(g_msg + (size_t)curd * CC + c), "f"(acc)
                             : "memory");
                acc  = 0.f;
                curd = dd;
                fd = __ldg(g_P + (size_t)curd * ZP + c);
                sd = __ldg(g_P + (size_t)curd * ZP + 256 + c);
            }
            int s = __ldg(g_srcp + j);       // uniform, sequential
            const ulonglong2* ewp = (const ulonglong2*)(g_ewc + (size_t)j * 16);
            ulonglong2 e0 = __ldg(ewp + 0), e1 = __ldg(ewp + 1);
            ulonglong2 e2 = __ldg(ewp + 2), e3 = __ldg(ewp + 3);
            float fs = __ldg(g_P + (size_t)s * ZP + 128 + c);   // coalesced 128B
            float ss = __ldg(g_P + (size_t)s * ZP + 384 + c);

            ull FF = 0, SS = 0;              // (0.f, 0.f) packed
            FF = fma2(e0.x, wf2[0], FF);  SS = fma2(e0.x, ws2[0], SS);
            FF = fma2(e0.y, wf2[1], FF);  SS = fma2(e0.y, ws2[1], SS);
            FF = fma2(e1.x, wf2[2], FF);  SS = fma2(e1.x, ws2[2], SS);
            FF = fma2(e1.y, wf2[3], FF);  SS = fma2(e1.y, ws2[3], SS);
            FF = fma2(e2.x, wf2[4], FF);  SS = fma2(e2.x, ws2[4], SS);
            FF = fma2(e2.y, wf2[5], FF);  SS = fma2(e2.y, ws2[5], SS);
            FF = fma2(e3.x, wf2[6], FF);  SS = fma2(e3.x, ws2[6], SS);
            FF = fma2(e3.y, wf2[7], FF);  SS = fma2(e3.y, ws2[7], SS);

            float flo, fhi, slo, shi;
            unpack2(FF, flo, fhi);
            unpack2(SS, slo, shi);
            float F = fd + fs + flo + fhi;
            float S = sd + ss + slo + shi;
            acc += sigm(F) * sftp(S);
        }

        asm volatile("red.global.add.f32 [%0], %1;"
                     :: "l"(g_msg + (size_t)curd * CC + c), "f"(acc)
                     : "memory");
    }
}

// ---------------------------------------------------------------------------
__global__ void combine_k(const float* __restrict__ h, float* __restrict__ o,
                          int n4, int relu) {
    const float4* h4 = (const float4*)h;
    const float4* m4 = (const float4*)g_msg;
    float4* o4 = (float4*)o;
    for (int i = blockIdx.x * blockDim.x + threadIdx.x; i < n4;
         i += gridDim.x * blockDim.x) {
        float4 a = h4[i], b = m4[i];
        a.x += b.x; a.y += b.y; a.z += b.z; a.w += b.w;
        if (relu) {
            a.x = fmaxf(a.x, 0.f); a.y = fmaxf(a.y, 0.f);
            a.z = fmaxf(a.z, 0.f); a.w = fmaxf(a.w, 0.f);
        }
        o4[i] = a;
    }
}

// ---------------------------------------------------------------------------
__global__ void colsum_k(const float* __restrict__ h, int M) {
    int c = threadIdx.x;   // 128 threads
    float loc = 0.f;
    for (int i = blockIdx.x; i < M; i += gridDim.x)
        loc += h[(size_t)i * CC + c];
    atomicAdd(&g_cs[c], loc);
}

__global__ void final_k(const float* __restrict__ Wlin,
                        const float* __restrict__ blin,
                        float* __restrict__ out, float invM) {
    int o = threadIdx.x;
    if (o < 64) {
        float a = 0.f;
#pragma unroll 4
        for (int c = 0; c < 128; c++) a += g_cs[c] * Wlin[o * 128 + c];
        out[o] = blin[o] + a * invM;
    }
}

// ---------------------------------------------------------------------------
extern "C" void kernel_launch(void* const* d_in, const int* in_sizes, int n_in,
                              void* d_out, int out_size) {
    const float* x    = (const float*)d_in[0];
    const void*  eidx = d_in[1];
    const float* ew   = (const float*)d_in[2];
    const float* Wf[3] = {(const float*)d_in[3], (const float*)d_in[7],  (const float*)d_in[11]};
    const float* bf[3] = {(const float*)d_in[4], (const float*)d_in[8],  (const float*)d_in[12]};
    const float* Ws[3] = {(const float*)d_in[5], (const float*)d_in[9],  (const float*)d_in[13]};
    const float* bs[3] = {(const float*)d_in[6], (const float*)d_in[10], (const float*)d_in[14]};
    const float* Wlin = (const float*)d_in[15];
    const float* blin = (const float*)d_in[16];
    float* out = (float*)d_out;

    int M = in_sizes[0] / 128;   // 50000
    int E = in_sizes[2] / 16;    // 800000

    float *hA, *hB, *msg, *cs;
    int *cur;
    cudaGetSymbolAddress((void**)&hA,  g_hA);
    cudaGetSymbolAddress((void**)&hB,  g_hB);
    cudaGetSymbolAddress((void**)&msg, g_msg);
    cudaGetSymbolAddress((void**)&cs,  g_cs);
    cudaGetSymbolAddress((void**)&cur, g_cur);

    const float* hin[3]  = {x, hA, hB};
    float*       hout[3] = {hA, hB, hA};

    dim3 ggrid((M + 63) / 64, 8);
    int nblk = (M + 255) / 256;
    int n4 = M * CC / 4;

    // ---- CSR build (once per launch) ----
    detect_k<<<1, 32>>>((const long long*)eidx, M);
    zero_int_k<<<256, 256>>>(cur, M);
    count_k<<<1024, 256>>>(eidx, E);
    scan1_k<<<nblk, 256>>>(M);
    scan2_k<<<1, 256>>>(nblk);
    scan3_k<<<nblk, 256>>>(M, E);
    scatter_k<<<1024, 256>>>(eidx, ew, E);

    // ---- 3 CGConv layers ----
    for (int l = 0; l < 3; l++) {
        pack_B<<<(ZP * CC + 255) / 256, 256>>>(Wf[l], Ws[l]);
        gemm_k<<<ggrid, 256>>>(hin[l], bf[l], bs[l], M);
        zero_k<<<1024, 256>>>(msg, n4);
        edge_k<<<2368, 256>>>(Wf[l], Ws[l], E);
        combine_k<<<1024, 256>>>(hin[l], hout[l], n4, (l < 2) ? 1 : 0);
    }

    // ---- mean pool + linear ----
    zero_k<<<1, 32>>>(cs, CC / 4);
    colsum_k<<<512, 128>>>(hA, M);
    final_k<<<1, 64>>>(Wlin, blin, out, 1.0f / (float)M);
}

// round 13
// speedup vs baseline: 1.6370x; 1.2677x over previous
#include <cuda_runtime.h>
#include <cstdint>

// SimpleGNN: 3x CGConv + mean-pool + linear.
// R13: R2 structure (best measured: warp-per-edge, smem weights, v4 RED) with
// (a) upgraded GEMM: 128x128 tile, 8x8/thread, f32x2 packed FMA (80 issue
//     slots/output vs 128), and
// (b) launch order arranged so edge_k is launch index 3 -> ncu finally
//     captures the hot kernel (empirically ncu grabs launch #3).

#define NN 50000
#define EE 800000
#define CC 128
#define ZP 512

typedef unsigned long long ull;

__device__ __align__(16) float g_P[(size_t)NN * ZP];   // node projections
__device__ __align__(16) float g_hA[(size_t)NN * CC];
__device__ __align__(16) float g_hB[(size_t)NN * CC];
__device__ __align__(16) float g_msg[(size_t)NN * CC]; // aggregated messages
__device__ __align__(16) float g_B[ZP * CC];           // packed node-projection weights
__device__ float g_cs[CC];                 // column sums for pooling
__device__ int   g_idx64;                  // 1 if edge_idx is int64, 0 if int32

// ---- f32x2 helpers (sm_100+) ----------------------------------------------
__device__ __forceinline__ ull pack2(float a, float b) {
    ull r; asm("mov.b64 %0, {%1, %2};" : "=l"(r) : "f"(a), "f"(b)); return r;
}
__device__ __forceinline__ void unpack2(ull v, float& a, float& b) {
    asm("mov.b64 {%0, %1}, %2;" : "=f"(a), "=f"(b) : "l"(v));
}
__device__ __forceinline__ ull fma2(ull a, ull b, ull c) {
    ull d; asm("fma.rn.f32x2 %0, %1, %2, %3;" : "=l"(d) : "l"(a), "l"(b), "l"(c));
    return d;
}

// ---------------------------------------------------------------------------
// layer-0 msg zero + edge-index dtype detection fused (keeps edge_k at launch
// index 3 for ncu capture).
__global__ void zero_detect_k(float* __restrict__ p, int n4,
                              const long long* __restrict__ e64, int N) {
    if (blockIdx.x == 0 && threadIdx.x == 0) {
        int ok64 = 1;
        for (int i = 0; i < 64; i++) {
            long long v = e64[i];
            if (v < 0 || v >= N) { ok64 = 0; break; }
        }
        g_idx64 = ok64;
    }
    float4* q = (float4*)p;
    for (int i = blockIdx.x * blockDim.x + threadIdx.x; i < n4;
         i += gridDim.x * blockDim.x)
        q[i] = make_float4(0.f, 0.f, 0.f, 0.f);
}

__global__ void zero_k(float* __restrict__ p, int n4) {
    float4* q = (float4*)p;
    for (int i = blockIdx.x * blockDim.x + threadIdx.x; i < n4;
         i += gridDim.x * blockDim.x)
        q[i] = make_float4(0.f, 0.f, 0.f, 0.f);
}

// ---------------------------------------------------------------------------
// pack the 512x128 node-projection weight matrix:
// rows   0..127 : Wf[:,   0:128] (dst f) | 128..255 : Wf[:,128:256] (src f)
// rows 256..383 : Ws[:,   0:128] (dst s) | 384..511 : Ws[:,128:256] (src s)
__global__ void pack_B(const float* __restrict__ Wf, const float* __restrict__ Ws) {
    int j = blockIdx.x * blockDim.x + threadIdx.x;
    if (j >= ZP * CC) return;
    int row  = j >> 7;
    int k    = j & 127;
    int c    = row & 127;
    int part = row >> 7;
    const float* W = (part < 2) ? Wf : Ws;
    int off = (part & 1) ? 128 : 0;
    g_B[j] = W[c * 272 + off + k];
}

// ---------------------------------------------------------------------------
// P[M,512] = H[M,128] @ g_B^T. 128x128 tile, 256 threads, 8x8 per thread,
// f32x2 packed FMA (b-pairs reinterpreted straight from smem).
__global__ void gemm_k(const float* __restrict__ H, int M) {
    __shared__ float As[16][132];
    __shared__ float Bs[16][132];
    int tid = threadIdx.x;
    int tx = tid & 15, ty = tid >> 4;
    int i0 = blockIdx.x * 128, j0 = blockIdx.y * 128;

    ull acc2[8][4];
#pragma unroll
    for (int r = 0; r < 8; r++)
#pragma unroll
        for (int p = 0; p < 4; p++) acc2[r][p] = 0ull;

    for (int k0 = 0; k0 < 128; k0 += 16) {
#pragma unroll
        for (int rep = 0; rep < 2; rep++) {
            int v   = tid + rep * 256;    // 0..511
            int row = v & 127;
            int kq  = v >> 7;             // 0..3
            float4 va = make_float4(0.f, 0.f, 0.f, 0.f);
            if (i0 + row < M)
                va = *(const float4*)(H + (size_t)(i0 + row) * 128 + k0 + kq * 4);
            As[kq * 4 + 0][row] = va.x; As[kq * 4 + 1][row] = va.y;
            As[kq * 4 + 2][row] = va.z; As[kq * 4 + 3][row] = va.w;
            float4 vb = *(const float4*)(g_B + (size_t)(j0 + row) * 128 + k0 + kq * 4);
            Bs[kq * 4 + 0][row] = vb.x; Bs[kq * 4 + 1][row] = vb.y;
            Bs[kq * 4 + 2][row] = vb.z; Bs[kq * 4 + 3][row] = vb.w;
        }
        __syncthreads();
#pragma unroll
        for (int kk = 0; kk < 16; kk++) {
            float4 a0 = *(const float4*)&As[kk][ty * 8];
            float4 a1 = *(const float4*)&As[kk][ty * 8 + 4];
            ull b0 = *(const ull*)&Bs[kk][tx * 8 + 0];
            ull b1 = *(const ull*)&Bs[kk][tx * 8 + 2];
            ull b2 = *(const ull*)&Bs[kk][tx * 8 + 4];
            ull b3 = *(const ull*)&Bs[kk][tx * 8 + 6];
            float a[8] = {a0.x, a0.y, a0.z, a0.w, a1.x, a1.y, a1.z, a1.w};
#pragma unroll
            for (int r = 0; r < 8; r++) {
                ull pa = pack2(a[r], a[r]);
                acc2[r][0] = fma2(pa, b0, acc2[r][0]);
                acc2[r][1] = fma2(pa, b1, acc2[r][1]);
                acc2[r][2] = fma2(pa, b2, acc2[r][2]);
                acc2[r][3] = fma2(pa, b3, acc2[r][3]);
            }
        }
        __syncthreads();
    }

#pragma unroll
    for (int r = 0; r < 8; r++) {
        int row = i0 + ty * 8 + r;
        if (row < M) {
            float o[8];
            unpack2(acc2[r][0], o[0], o[1]);
            unpack2(acc2[r][1], o[2], o[3]);
            unpack2(acc2[r][2], o[4], o[5]);
            unpack2(acc2[r][3], o[6], o[7]);
            float* dst = g_P + (size_t)row * ZP + j0 + tx * 8;
            *(float4*)(dst + 0) = make_float4(o[0], o[1], o[2], o[3]);
            *(float4*)(dst + 4) = make_float4(o[4], o[5], o[6], o[7]);
        }
    }
}

// ---------------------------------------------------------------------------
__device__ __forceinline__ float sigm(float x) {
    return __fdividef(1.f, 1.f + __expf(-x));
}
__device__ __forceinline__ float sftp(float x) {
    return fmaxf(x, 0.f) + __logf(1.f + __expf(-fabsf(x)));
}

// ---------------------------------------------------------------------------
// R2's edge kernel (best measured). One warp per edge; lane l owns channels
// 4l..4l+3; smem-resident edge-attr weights; red.global.add.v4.f32 scatter.
__global__ void edge_k(const void* __restrict__ eidx_raw,
                       const float* __restrict__ ew,
                       const float* __restrict__ Wf, const float* __restrict__ Ws,
                       const float* __restrict__ bf, const float* __restrict__ bs,
                       int E) {
    __shared__ float4 wfe[16][32];   // [k][lane] = Wf[4l..4l+3][256+k]
    __shared__ float4 wse[16][32];
    __shared__ float4 bfv[32], bsv[32];
    int tid = threadIdx.x;
    for (int idx = tid; idx < 512; idx += blockDim.x) {
        int k = idx >> 5, l = idx & 31, c0 = l << 2;
        wfe[k][l] = make_float4(Wf[(c0 + 0) * 272 + 256 + k],
                                Wf[(c0 + 1) * 272 + 256 + k],
                                Wf[(c0 + 2) * 272 + 256 + k],
                                Wf[(c0 + 3) * 272 + 256 + k]);
        wse[k][l] = make_float4(Ws[(c0 + 0) * 272 + 256 + k],
                                Ws[(c0 + 1) * 272 + 256 + k],
                                Ws[(c0 + 2) * 272 + 256 + k],
                                Ws[(c0 + 3) * 272 + 256 + k]);
    }
    if (tid < 32) {
        bfv[tid] = *(const float4*)(bf + tid * 4);
        bsv[tid] = *(const float4*)(bs + tid * 4);
    }
    __syncthreads();

    const int is64 = g_idx64;
    const long long* e64 = (const long long*)eidx_raw;
    const int*       e32 = (const int*)eidx_raw;

    int lane = tid & 31;
    int warp = blockIdx.x * (blockDim.x >> 5) + (tid >> 5);
    int nw   = gridDim.x * (blockDim.x >> 5);
    float4 bF = bfv[lane], bS = bsv[lane];

    for (int e = warp; e < E; e += nw) {
        int s, d;
        if (is64) {
            s = (int)__ldg(e64 + e);
            d = (int)__ldg(e64 + E + e);
        } else {
            s = __ldg(e32 + e);
            d = __ldg(e32 + E + e);
        }
        const float4* ewp = (const float4*)(ew + (size_t)e * 16);
        float4 e0 = ewp[0], e1 = ewp[1], e2 = ewp[2], e3 = ewp[3];
        float ev[16] = {e0.x, e0.y, e0.z, e0.w, e1.x, e1.y, e1.z, e1.w,
                        e2.x, e2.y, e2.z, e2.w, e3.x, e3.y, e3.z, e3.w};

        const float* Pd = g_P + (size_t)d * ZP;
        const float* Ps = g_P + (size_t)s * ZP;
        float4 fd = *(const float4*)(Pd + lane * 4);
        float4 fs = *(const float4*)(Ps + 128 + lane * 4);
        float4 sd = *(const float4*)(Pd + 256 + lane * 4);
        float4 ss = *(const float4*)(Ps + 384 + lane * 4);

        float4 F, S;
        F.x = fd.x + fs.x + bF.x; F.y = fd.y + fs.y + bF.y;
        F.z = fd.z + fs.z + bF.z; F.w = fd.w + fs.w + bF.w;
        S.x = sd.x + ss.x + bS.x; S.y = sd.y + ss.y + bS.y;
        S.z = sd.z + ss.z + bS.z; S.w = sd.w + ss.w + bS.w;

#pragma unroll
        for (int k = 0; k < 16; k++) {
            float w = ev[k];
            float4 a = wfe[k][lane];
            F.x = fmaf(w, a.x, F.x); F.y = fmaf(w, a.y, F.y);
            F.z = fmaf(w, a.z, F.z); F.w = fmaf(w, a.w, F.w);
            float4 b = wse[k][lane];
            S.x = fmaf(w, b.x, S.x); S.y = fmaf(w, b.y, S.y);
            S.z = fmaf(w, b.z, S.z); S.w = fmaf(w, b.w, S.w);
        }
        float4 m;
        m.x = sigm(F.x) * sftp(S.x);
        m.y = sigm(F.y) * sftp(S.y);
        m.z = sigm(F.z) * sftp(S.z);
        m.w = sigm(F.w) * sftp(S.w);

        float* outp = g_msg + (size_t)d * CC + lane * 4;
        asm volatile("red.global.add.v4.f32 [%0], {%1,%2,%3,%4};"
                     :: "l"(outp), "f"(m.x), "f"(m.y), "f"(m.z), "f"(m.w)
                     : "memory");
    }
}

// ---------------------------------------------------------------------------
__global__ void combine_k(const float* __restrict__ h, float* __restrict__ o,
                          int n4, int relu) {
    const float4* h4 = (const float4*)h;
    const float4* m4 = (const float4*)g_msg;
    float4* o4 = (float4*)o;
    for (int i = blockIdx.x * blockDim.x + threadIdx.x; i < n4;
         i += gridDim.x * blockDim.x) {
        float4 a = h4[i], b = m4[i];
        a.x += b.x; a.y += b.y; a.z += b.z; a.w += b.w;
        if (relu) {
            a.x = fmaxf(a.x, 0.f); a.y = fmaxf(a.y, 0.f);
            a.z = fmaxf(a.z, 0.f); a.w = fmaxf(a.w, 0.f);
        }
        o4[i] = a;
    }
}

// ---------------------------------------------------------------------------
__global__ void colsum_k(const float* __restrict__ h, int M) {
    int c = threadIdx.x;   // 128 threads
    float loc = 0.f;
    for (int i = blockIdx.x; i < M; i += gridDim.x)
        loc += h[(size_t)i * CC + c];
    atomicAdd(&g_cs[c], loc);
}

__global__ void final_k(const float* __restrict__ Wlin,
                        const float* __restrict__ blin,
                        float* __restrict__ out, float invM) {
    int o = threadIdx.x;
    if (o < 64) {
        float a = 0.f;
#pragma unroll 4
        for (int c = 0; c < 128; c++) a += g_cs[c] * Wlin[o * 128 + c];
        out[o] = blin[o] + a * invM;
    }
}

// ---------------------------------------------------------------------------
extern "C" void kernel_launch(void* const* d_in, const int* in_sizes, int n_in,
                              void* d_out, int out_size) {
    const float* x    = (const float*)d_in[0];
    const void*  eidx = d_in[1];
    const float* ew   = (const float*)d_in[2];
    const float* Wf[3] = {(const float*)d_in[3], (const float*)d_in[7],  (const float*)d_in[11]};
    const float* bf[3] = {(const float*)d_in[4], (const float*)d_in[8],  (const float*)d_in[12]};
    const float* Ws[3] = {(const float*)d_in[5], (const float*)d_in[9],  (const float*)d_in[13]};
    const float* bs[3] = {(const float*)d_in[6], (const float*)d_in[10], (const float*)d_in[14]};
    const float* Wlin = (const float*)d_in[15];
    const float* blin = (const float*)d_in[16];
    float* out = (float*)d_out;

    int M = in_sizes[0] / 128;   // 50000
    int E = in_sizes[2] / 16;    // 800000

    float *hA, *hB, *msg, *cs;
    cudaGetSymbolAddress((void**)&hA,  g_hA);
    cudaGetSymbolAddress((void**)&hB,  g_hB);
    cudaGetSymbolAddress((void**)&msg, g_msg);
    cudaGetSymbolAddress((void**)&cs,  g_cs);

    const float* hin[3]  = {x, hA, hB};
    float*       hout[3] = {hA, hB, hA};

    dim3 ggrid((M + 127) / 128, ZP / 128);
    int n4 = M * CC / 4;

    // ---- layer 0, ordered so edge_k is launch index 3 (ncu capture) ----
    zero_detect_k<<<1024, 256>>>(msg, n4, (const long long*)eidx, M);   // 0
    pack_B<<<(ZP * CC + 255) / 256, 256>>>(Wf[0], Ws[0]);               // 1
    gemm_k<<<ggrid, 256>>>(x, M);                                       // 2
    edge_k<<<1184, 256>>>(eidx, ew, Wf[0], Ws[0], bf[0], bs[0], E);     // 3
    combine_k<<<1024, 256>>>(x, hA, n4, 1);                             // 4

    // ---- layers 1, 2 ----
    for (int l = 1; l < 3; l++) {
        pack_B<<<(ZP * CC + 255) / 256, 256>>>(Wf[l], Ws[l]);
        gemm_k<<<ggrid, 256>>>(hin[l], M);
        zero_k<<<1024, 256>>>(msg, n4);
        edge_k<<<1184, 256>>>(eidx, ew, Wf[l], Ws[l], bf[l], bs[l], E);
        combine_k<<<1024, 256>>>(hin[l], hout[l], n4, (l < 2) ? 1 : 0);
    }

    // ---- mean pool + linear ----
    zero_k<<<1, 32>>>(cs, CC / 4);
    colsum_k<<<512, 128>>>(hA, M);
    final_k<<<1, 64>>>(Wlin, blin, out, 1.0f / (float)M);
}